// round 5
// baseline (speedup 1.0000x reference)
#include <cuda_runtime.h>
#include <cuda_bf16.h>

#define Bn 4
#define Sn 4096
#define Hn 2048
#define EPSf 1e-6f

#define CS 16              // s-rows produced per block
#define NROWS (CS + 3)     // +3 causal halo

// ---------------------------------------------------------------------------
// Fused RMSNorm + depthwise causal conv1d (K=4) + bias. One DRAM pass over x.
// grid = (S/CS, B), block = 512, 3 blocks/SM (reg cap 42).
// Phase 1: 16 warps compute per-row inv_rms for the CS+3 window (DRAM read).
// Phase 2: thread owns one float4 H-column, rolling 3-deep window (L2 re-read),
//          norm_weight folded into conv taps, streaming stores.
// ---------------------------------------------------------------------------
__global__ __launch_bounds__(512, 3) void fused_kernel(const float* __restrict__ x,
                                                       const float* __restrict__ nw,
                                                       const float* __restrict__ cw,
                                                       const float* __restrict__ cb,
                                                       float*       __restrict__ out) {
    __shared__ float s_ir[NROWS];

    const int b    = blockIdx.y;
    const int s0   = blockIdx.x * CS;
    const int tid  = threadIdx.x;
    const int warp = tid >> 5;
    const int lane = tid & 31;

    const float* xb = x   + (size_t)b * Sn * Hn;
    float*       ob = out + (size_t)b * Sn * Hn;

    // ---- Phase 1: inv_rms for rows s0-3 .. s0+CS-1 ----
    for (int j = warp; j < NROWS; j += 16) {
        const int s = s0 - 3 + j;
        float a0 = 0.f, a1 = 0.f;
        if (s >= 0) {
            const float4* xr = reinterpret_cast<const float4*>(xb + (size_t)s * Hn);
#pragma unroll
            for (int i = 0; i < 16; i += 2) {
                float4 v0 = xr[lane + 32 * (i + 0)];
                float4 v1 = xr[lane + 32 * (i + 1)];
                a0 = fmaf(v0.x, v0.x, fmaf(v0.y, v0.y, fmaf(v0.z, v0.z, fmaf(v0.w, v0.w, a0))));
                a1 = fmaf(v1.x, v1.x, fmaf(v1.y, v1.y, fmaf(v1.z, v1.z, fmaf(v1.w, v1.w, a1))));
            }
        }
        float ss = a0 + a1;
#pragma unroll
        for (int o = 16; o; o >>= 1)
            ss += __shfl_xor_sync(0xFFFFFFFFu, ss, o);
        if (lane == 0)
            s_ir[j] = (s >= 0) ? rsqrtf(ss * (1.0f / (float)Hn) + EPSf) : 0.0f;
    }
    __syncthreads();

    // ---- Phase 2: conv over rows s0 .. s0+CS-1, thread owns float4 column h4=tid ----
    const int h4 = tid;                 // 0..511
    const int h  = h4 * 4;

    // Taps with norm_weight folded in: (w_k * nw_h). Window then stores v*r only.
    const float4* cw4 = reinterpret_cast<const float4*>(cw);
    const float4 nwv = __ldg(&reinterpret_cast<const float4*>(nw)[h4]);
    float4 t0 = __ldg(&cw4[h + 0]);
    float4 t1 = __ldg(&cw4[h + 1]);
    float4 t2 = __ldg(&cw4[h + 2]);
    float4 t3 = __ldg(&cw4[h + 3]);
    t0.x *= nwv.x; t0.y *= nwv.x; t0.z *= nwv.x; t0.w *= nwv.x;
    t1.x *= nwv.y; t1.y *= nwv.y; t1.z *= nwv.y; t1.w *= nwv.y;
    t2.x *= nwv.z; t2.y *= nwv.z; t2.z *= nwv.z; t2.w *= nwv.z;
    t3.x *= nwv.w; t3.y *= nwv.w; t3.z *= nwv.w; t3.w *= nwv.w;
    const float4 bias = __ldg(&reinterpret_cast<const float4*>(cb)[h4]);

    // Rolling window of v*r for rows s0-3, s0-2, s0-1
    float4 xm3, xm2, xm1;
    {
        float4 pre[3];
#pragma unroll
        for (int j = 0; j < 3; j++) {
            const int s = s0 - 3 + j;
            if (s >= 0) {
                float4 v = reinterpret_cast<const float4*>(xb + (size_t)s * Hn)[h4];
                const float r = s_ir[j];
                pre[j].x = v.x * r;
                pre[j].y = v.y * r;
                pre[j].z = v.z * r;
                pre[j].w = v.w * r;
            } else {
                pre[j] = make_float4(0.f, 0.f, 0.f, 0.f);
            }
        }
        xm3 = pre[0]; xm2 = pre[1]; xm1 = pre[2];
    }

#pragma unroll 4
    for (int j = 0; j < CS; j++) {
        const int s = s0 + j;
        float4 v = reinterpret_cast<const float4*>(xb + (size_t)s * Hn)[h4];
        const float r = s_ir[j + 3];
        float4 xn;
        xn.x = v.x * r;
        xn.y = v.y * r;
        xn.z = v.z * r;
        xn.w = v.w * r;

        float4 y;
        y.x = fmaf(t0.x, xm3.x, fmaf(t0.y, xm2.x, fmaf(t0.z, xm1.x, fmaf(t0.w, xn.x, bias.x))));
        y.y = fmaf(t1.x, xm3.y, fmaf(t1.y, xm2.y, fmaf(t1.z, xm1.y, fmaf(t1.w, xn.y, bias.y))));
        y.z = fmaf(t2.x, xm3.z, fmaf(t2.y, xm2.z, fmaf(t2.z, xm1.z, fmaf(t2.w, xn.z, bias.z))));
        y.w = fmaf(t3.x, xm3.w, fmaf(t3.y, xm2.w, fmaf(t3.z, xm1.w, fmaf(t3.w, xn.w, bias.w))));

        // Streaming store: output is never re-read; don't pollute L2.
        __stcs(reinterpret_cast<float4*>(ob + (size_t)s * Hn) + h4, y);

        xm3 = xm2; xm2 = xm1; xm1 = xn;
    }
}

// ---------------------------------------------------------------------------
// Inputs (metadata order): hidden_states, norm_weight, conv_weight, conv_bias
// ---------------------------------------------------------------------------
extern "C" void kernel_launch(void* const* d_in, const int* in_sizes, int n_in,
                              void* d_out, int out_size) {
    const float* x  = (const float*)d_in[0];
    const float* nw = (const float*)d_in[1];
    const float* cw = (const float*)d_in[2];
    const float* cb = (const float*)d_in[3];
    float* out = (float*)d_out;

    dim3 grid(Sn / CS, Bn);
    fused_kernel<<<grid, 512>>>(x, nw, cw, cb, out);
}

// round 7
// speedup vs baseline: 1.2537x; 1.2537x over previous
#include <cuda_runtime.h>
#include <cuda_bf16.h>

#define Bn 4
#define Sn 4096
#define Hn 2048
#define H4 (Hn / 4)
#define EPSf 1e-6f

#define RS 16              // rows per block
#define CSr 4              // rows per chunk (register-resident)

__device__ __forceinline__ float warp_sum(float v) {
#pragma unroll
    for (int o = 16; o; o >>= 1)
        v += __shfl_xor_sync(0xFFFFFFFFu, v, o);
    return v;
}

__device__ __forceinline__ float dot4(const float4 v) {
    return fmaf(v.x, v.x, fmaf(v.y, v.y, fmaf(v.z, v.z, v.w * v.w)));
}

// ---------------------------------------------------------------------------
// Fused RMSNorm + depthwise causal conv1d (K=4) + bias, register-resident.
// Thread owns one float4 H-column; block owns 16 rows, chunked by 4.
// Each row of x is read from DRAM exactly once into registers; the reduction
// and the conv both consume those registers (no L2 re-read). Streaming stores.
// grid = (S/RS, B) = 1024 blocks, block = 512, occ 2.
// ---------------------------------------------------------------------------
__global__ __launch_bounds__(512, 2) void fused_kernel(const float* __restrict__ x,
                                                       const float* __restrict__ nw,
                                                       const float* __restrict__ cw,
                                                       const float* __restrict__ cb,
                                                       float*       __restrict__ out) {
    __shared__ float s_part[CSr * 16];   // [row][warp] partial sums
    __shared__ float s_ir[CSr];          // per-chunk inv_rms
    __shared__ float s_hir[3];           // halo inv_rms

    const int b    = blockIdx.y;
    const int s0   = blockIdx.x * RS;
    const int tid  = threadIdx.x;
    const int warp = tid >> 5;
    const int lane = tid & 31;

    const float* xb = x   + (size_t)b * Sn * Hn;
    float*       ob = out + (size_t)b * Sn * Hn;

    // ---- halo inv_rms: warps 0..2 reduce rows s0-3..s0-1 from GMEM ----
    if (warp < 3) {
        const int s = s0 - 3 + warp;
        float a0 = 0.f, a1 = 0.f;
        if (s >= 0) {
            const float4* xr = reinterpret_cast<const float4*>(xb + (size_t)s * Hn);
#pragma unroll
            for (int i = 0; i < 16; i += 2) {
                float4 v0 = xr[lane + 32 * (i + 0)];
                float4 v1 = xr[lane + 32 * (i + 1)];
                a0 += dot4(v0);
                a1 += dot4(v1);
            }
        }
        float ss = warp_sum(a0 + a1);
        if (lane == 0)
            s_hir[warp] = (s >= 0) ? rsqrtf(ss * (1.0f / (float)Hn) + EPSf) : 0.0f;
    }
    __syncthreads();

    // ---- per-thread constants: taps (norm_weight folded), bias ----
    const int h4 = tid;
    const int h  = h4 * 4;
    const float4* cw4 = reinterpret_cast<const float4*>(cw);
    const float4 nwv = __ldg(&reinterpret_cast<const float4*>(nw)[h4]);
    float4 t0 = __ldg(&cw4[h + 0]);
    float4 t1 = __ldg(&cw4[h + 1]);
    float4 t2 = __ldg(&cw4[h + 2]);
    float4 t3 = __ldg(&cw4[h + 3]);
    t0.x *= nwv.x; t0.y *= nwv.x; t0.z *= nwv.x; t0.w *= nwv.x;
    t1.x *= nwv.y; t1.y *= nwv.y; t1.z *= nwv.y; t1.w *= nwv.y;
    t2.x *= nwv.z; t2.y *= nwv.z; t2.z *= nwv.z; t2.w *= nwv.z;
    t3.x *= nwv.w; t3.y *= nwv.w; t3.z *= nwv.w; t3.w *= nwv.w;
    const float4 bias = __ldg(&reinterpret_cast<const float4*>(cb)[h4]);

    // ---- rolling window from halo rows (mostly L2 hits; 3 rows only) ----
    float4 xm3, xm2, xm1;
    {
        float4 pre[3];
#pragma unroll
        for (int j = 0; j < 3; j++) {
            const int s = s0 - 3 + j;
            if (s >= 0) {
                float4 v = reinterpret_cast<const float4*>(xb + (size_t)s * Hn)[h4];
                const float r = s_hir[j];
                pre[j].x = v.x * r; pre[j].y = v.y * r; pre[j].z = v.z * r; pre[j].w = v.w * r;
            } else {
                pre[j] = make_float4(0.f, 0.f, 0.f, 0.f);
            }
        }
        xm3 = pre[0]; xm2 = pre[1]; xm1 = pre[2];
    }

    // ---- main loop: 4 chunks of 4 rows, register-resident ----
#pragma unroll 1
    for (int c = 0; c < RS / CSr; c++) {
        const int sb = s0 + c * CSr;
        const float4* base = reinterpret_cast<const float4*>(xb + (size_t)sb * Hn) + h4;

        float4 v0 = base[0 * H4];
        float4 v1 = base[1 * H4];
        float4 v2 = base[2 * H4];
        float4 v3 = base[3 * H4];

        float q0 = warp_sum(dot4(v0));
        float q1 = warp_sum(dot4(v1));
        float q2 = warp_sum(dot4(v2));
        float q3 = warp_sum(dot4(v3));
        if (lane == 0) {
            s_part[0 * 16 + warp] = q0;
            s_part[1 * 16 + warp] = q1;
            s_part[2 * 16 + warp] = q2;
            s_part[3 * 16 + warp] = q3;
        }
        __syncthreads();

        if (tid < CSr) {
            float ssum = 0.f;
#pragma unroll
            for (int w = 0; w < 16; w++)
                ssum += s_part[tid * 16 + w];
            s_ir[tid] = rsqrtf(ssum * (1.0f / (float)Hn) + EPSf);
        }
        __syncthreads();

        const float r0 = s_ir[0];
        const float r1 = s_ir[1];
        const float r2 = s_ir[2];
        const float r3 = s_ir[3];

        float4* obase = reinterpret_cast<float4*>(ob + (size_t)sb * Hn) + h4;

#define CONV_ROW(VV, RR, ROWIDX)                                                               \
        {                                                                                      \
            float4 xn;                                                                         \
            xn.x = (VV).x * (RR); xn.y = (VV).y * (RR);                                        \
            xn.z = (VV).z * (RR); xn.w = (VV).w * (RR);                                        \
            float4 y;                                                                          \
            y.x = fmaf(t0.x, xm3.x, fmaf(t0.y, xm2.x, fmaf(t0.z, xm1.x, fmaf(t0.w, xn.x, bias.x)))); \
            y.y = fmaf(t1.x, xm3.y, fmaf(t1.y, xm2.y, fmaf(t1.z, xm1.y, fmaf(t1.w, xn.y, bias.y)))); \
            y.z = fmaf(t2.x, xm3.z, fmaf(t2.y, xm2.z, fmaf(t2.z, xm1.z, fmaf(t2.w, xn.z, bias.z)))); \
            y.w = fmaf(t3.x, xm3.w, fmaf(t3.y, xm2.w, fmaf(t3.z, xm1.w, fmaf(t3.w, xn.w, bias.w)))); \
            __stcs(obase + (ROWIDX) * H4, y);                                                  \
            xm3 = xm2; xm2 = xm1; xm1 = xn;                                                    \
        }

        CONV_ROW(v0, r0, 0)
        CONV_ROW(v1, r1, 1)
        CONV_ROW(v2, r2, 2)
        CONV_ROW(v3, r3, 3)
#undef CONV_ROW
    }
}

// ---------------------------------------------------------------------------
// Inputs (metadata order): hidden_states, norm_weight, conv_weight, conv_bias
// ---------------------------------------------------------------------------
extern "C" void kernel_launch(void* const* d_in, const int* in_sizes, int n_in,
                              void* d_out, int out_size) {
    const float* x  = (const float*)d_in[0];
    const float* nw = (const float*)d_in[1];
    const float* cw = (const float*)d_in[2];
    const float* cb = (const float*)d_in[3];
    float* out = (float*)d_out;

    dim3 grid(Sn / RS, Bn);
    fused_kernel<<<grid, 512>>>(x, nw, cw, cb, out);
}

// round 8
// speedup vs baseline: 1.3523x; 1.0786x over previous
#include <cuda_runtime.h>
#include <cuda_bf16.h>

#define Bn 4
#define Sn 4096
#define Hn 2048
#define H4 (Hn / 4)
#define EPSf 1e-6f

#define CS 16               // s-rows produced per block
#define NROWS (CS + 3)      // +3 causal halo
#define NQ (NROWS * 4)      // 76 quarter-rows

__device__ __forceinline__ float warp_sum(float v) {
#pragma unroll
    for (int o = 16; o; o >>= 1)
        v += __shfl_xor_sync(0xFFFFFFFFu, v, o);
    return v;
}

__device__ __forceinline__ float dot4(const float4 v) {
    return fmaf(v.x, v.x, fmaf(v.y, v.y, fmaf(v.z, v.z, v.w * v.w)));
}

// ---------------------------------------------------------------------------
// Fused RMSNorm + depthwise causal conv1d (K=4) + bias.
// grid = (S/CS, B) = 1024 blocks, block = 512, occ 2.
// Phase 1: 76 quarter-rows over 16 warps (balanced, 5-vs-4 items) -> partial
//          sums in smem -> 19 threads finish inv_rms. DRAM read happens here.
// Phase 2: thread owns one float4 H-column, rolling 3-deep window; the x
//          re-read hits L2. norm_weight folded into taps; streaming stores.
// ---------------------------------------------------------------------------
__global__ __launch_bounds__(512, 2) void fused_kernel(const float* __restrict__ x,
                                                       const float* __restrict__ nw,
                                                       const float* __restrict__ cw,
                                                       const float* __restrict__ cb,
                                                       float*       __restrict__ out) {
    __shared__ float s_part[NQ];     // per-quarter partial sums
    __shared__ float s_ir[NROWS];    // per-row inv_rms

    const int b    = blockIdx.y;
    const int s0   = blockIdx.x * CS;
    const int tid  = threadIdx.x;
    const int warp = tid >> 5;
    const int lane = tid & 31;

    const float* xb = x   + (size_t)b * Sn * Hn;
    float*       ob = out + (size_t)b * Sn * Hn;

    // ---- Phase 1a: quarter-row partial sums (balanced across warps) ----
    for (int q = warp; q < NQ; q += 16) {
        const int j = q >> 2;        // window row 0..18
        const int k = q & 3;         // quarter 0..3
        const int s = s0 - 3 + j;
        float a0 = 0.f, a1 = 0.f;
        if (s >= 0) {
            const float4* xr = reinterpret_cast<const float4*>(xb + (size_t)s * Hn) + k * 128;
            float4 v0 = xr[lane +  0];
            float4 v1 = xr[lane + 32];
            float4 v2 = xr[lane + 64];
            float4 v3 = xr[lane + 96];
            a0 = dot4(v0) + dot4(v2);
            a1 = dot4(v1) + dot4(v3);
        }
        float ss = warp_sum(a0 + a1);
        if (lane == 0)
            s_part[q] = ss;
    }
    __syncthreads();

    // ---- Phase 1b: finish per-row inv_rms ----
    if (tid < NROWS) {
        const int s = s0 - 3 + tid;
        float ssum = (s_part[tid * 4 + 0] + s_part[tid * 4 + 1]) +
                     (s_part[tid * 4 + 2] + s_part[tid * 4 + 3]);
        s_ir[tid] = (s >= 0) ? rsqrtf(ssum * (1.0f / (float)Hn) + EPSf) : 0.0f;
    }
    __syncthreads();

    // ---- Phase 2: conv over rows s0 .. s0+CS-1, thread owns float4 column h4=tid ----
    const int h4 = tid;              // 0..511
    const int h  = h4 * 4;

    // Taps with norm_weight folded in: (w_k * nw_h). Window then stores v*r only.
    const float4* cw4 = reinterpret_cast<const float4*>(cw);
    const float4 nwv = __ldg(&reinterpret_cast<const float4*>(nw)[h4]);
    float4 t0 = __ldg(&cw4[h + 0]);
    float4 t1 = __ldg(&cw4[h + 1]);
    float4 t2 = __ldg(&cw4[h + 2]);
    float4 t3 = __ldg(&cw4[h + 3]);
    t0.x *= nwv.x; t0.y *= nwv.x; t0.z *= nwv.x; t0.w *= nwv.x;
    t1.x *= nwv.y; t1.y *= nwv.y; t1.z *= nwv.y; t1.w *= nwv.y;
    t2.x *= nwv.z; t2.y *= nwv.z; t2.z *= nwv.z; t2.w *= nwv.z;
    t3.x *= nwv.w; t3.y *= nwv.w; t3.z *= nwv.w; t3.w *= nwv.w;
    const float4 bias = __ldg(&reinterpret_cast<const float4*>(cb)[h4]);

    // Rolling window of v*r for rows s0-3, s0-2, s0-1
    float4 xm3, xm2, xm1;
    {
        float4 pre[3];
#pragma unroll
        for (int j = 0; j < 3; j++) {
            const int s = s0 - 3 + j;
            if (s >= 0) {
                float4 v = reinterpret_cast<const float4*>(xb + (size_t)s * Hn)[h4];
                const float r = s_ir[j];
                pre[j].x = v.x * r;
                pre[j].y = v.y * r;
                pre[j].z = v.z * r;
                pre[j].w = v.w * r;
            } else {
                pre[j] = make_float4(0.f, 0.f, 0.f, 0.f);
            }
        }
        xm3 = pre[0]; xm2 = pre[1]; xm1 = pre[2];
    }

#pragma unroll 4
    for (int j = 0; j < CS; j++) {
        const int s = s0 + j;
        float4 v = reinterpret_cast<const float4*>(xb + (size_t)s * Hn)[h4];
        const float r = s_ir[j + 3];
        float4 xn;
        xn.x = v.x * r;
        xn.y = v.y * r;
        xn.z = v.z * r;
        xn.w = v.w * r;

        float4 y;
        y.x = fmaf(t0.x, xm3.x, fmaf(t0.y, xm2.x, fmaf(t0.z, xm1.x, fmaf(t0.w, xn.x, bias.x))));
        y.y = fmaf(t1.x, xm3.y, fmaf(t1.y, xm2.y, fmaf(t1.z, xm1.y, fmaf(t1.w, xn.y, bias.y))));
        y.z = fmaf(t2.x, xm3.z, fmaf(t2.y, xm2.z, fmaf(t2.z, xm1.z, fmaf(t2.w, xn.z, bias.z))));
        y.w = fmaf(t3.x, xm3.w, fmaf(t3.y, xm2.w, fmaf(t3.z, xm1.w, fmaf(t3.w, xn.w, bias.w))));

        // Streaming store: output is never re-read; don't pollute L2.
        __stcs(reinterpret_cast<float4*>(ob + (size_t)s * Hn) + h4, y);

        xm3 = xm2; xm2 = xm1; xm1 = xn;
    }
}

// ---------------------------------------------------------------------------
// Inputs (metadata order): hidden_states, norm_weight, conv_weight, conv_bias
// ---------------------------------------------------------------------------
extern "C" void kernel_launch(void* const* d_in, const int* in_sizes, int n_in,
                              void* d_out, int out_size) {
    const float* x  = (const float*)d_in[0];
    const float* nw = (const float*)d_in[1];
    const float* cw = (const float*)d_in[2];
    const float* cb = (const float*)d_in[3];
    float* out = (float*)d_out;

    dim3 grid(Sn / CS, Bn);
    fused_kernel<<<grid, 512>>>(x, nw, cw, cb, out);
}